// round 6
// baseline (speedup 1.0000x reference)
#include <cuda_runtime.h>
#include <math.h>

#define B_SAMPLES 16384
#define EMB 64

__device__ int g_p_off[B_SAMPLES + 1];
__device__ int g_w_off[B_SAMPLES + 1];

// Boundary-scan offsets: for sorted seg, off[v] = lower_bound(seg, v).
__device__ __forceinline__ void scan_one(const int* __restrict__ seg, int T,
                                         int* __restrict__ off, int i)
{
    int cur = __ldg(seg + i);
    int prev = (i == 0) ? -1 : __ldg(seg + i - 1);
    for (int v = prev + 1; v <= cur; v++) off[v] = i;
    if (i == T - 1) {
        for (int v = cur + 1; v <= B_SAMPLES; v++) off[v] = T;
    }
}

__global__ void __launch_bounds__(256) offsets_kernel(
    const int* __restrict__ p_seg, int TP,
    const int* __restrict__ w_seg, int TW)
{
    int t = blockIdx.x * blockDim.x + threadIdx.x;
    if (t < TP) {
        scan_one(p_seg, TP, g_p_off, t);
    } else if (t < TP + TW) {
        scan_one(w_seg, TW, g_w_off, t - TP);
    }
}

// Warp gather: coalesced idx load + shfl broadcast; 8 independent row loads
// in flight per step (MLP=8).
__device__ __forceinline__ void gather_shfl(
    const int* __restrict__ idx, int s, int e,
    const float2* __restrict__ t2, int lane,
    float& ax, float& ay)
{
    float sx[8], sy[8];
    #pragma unroll
    for (int k = 0; k < 8; k++) { sx[k] = 0.f; sy[k] = 0.f; }

    int i = s;
    while (i + 32 <= e) {
        int c = __ldg(idx + i + lane);
        #pragma unroll
        for (int k0 = 0; k0 < 32; k0 += 8) {
            int r[8];
            #pragma unroll
            for (int k = 0; k < 8; k++)
                r[k] = __shfl_sync(0xFFFFFFFFu, c, k0 + k);
            float2 v[8];
            #pragma unroll
            for (int k = 0; k < 8; k++)
                v[k] = __ldg(t2 + (size_t)r[k] * 32 + lane);
            #pragma unroll
            for (int k = 0; k < 8; k++) { sx[k] += v[k].x; sy[k] += v[k].y; }
        }
        i += 32;
    }

    const int rem = e - i;
    if (rem > 0) {
        int pos = i + (lane < rem ? lane : rem - 1);   // clamp: in-bounds
        int c = __ldg(idx + pos);
        int k = 0;
        for (; k + 8 <= rem; k += 8) {
            int r[8];
            #pragma unroll
            for (int j = 0; j < 8; j++)
                r[j] = __shfl_sync(0xFFFFFFFFu, c, k + j);
            float2 v[8];
            #pragma unroll
            for (int j = 0; j < 8; j++)
                v[j] = __ldg(t2 + (size_t)r[j] * 32 + lane);
            #pragma unroll
            for (int j = 0; j < 8; j++) { sx[j] += v[j].x; sy[j] += v[j].y; }
        }
        for (; k < rem; k++) {
            int r = __shfl_sync(0xFFFFFFFFu, c, k);
            float2 v = __ldg(t2 + (size_t)r * 32 + lane);
            sx[0] += v.x; sy[0] += v.y;
        }
    }

    ax = ((sx[0] + sx[1]) + (sx[2] + sx[3])) + ((sx[4] + sx[5]) + (sx[6] + sx[7]));
    ay = ((sy[0] + sy[1]) + (sy[2] + sy[3])) + ((sy[4] + sy[5]) + (sy[6] + sy[7]));
}

// Two warps per sample: even warp gathers p-table, odd warp gathers w-table.
// Combine through shared memory; even warp finishes the dot + output.
__global__ void __launch_bounds__(256) svdpp_kernel(
    const int* __restrict__ sci_ids,
    const int* __restrict__ pap_ids,
    const int* __restrict__ p_idx,
    const int* __restrict__ w_idx,
    const float* __restrict__ s_fact,
    const float* __restrict__ p_fact,
    const float* __restrict__ s_bias,
    const float* __restrict__ p_bias,
    const float* __restrict__ imp_fact,
    const float* __restrict__ imp_wish,
    const float* __restrict__ g_bias,
    float* __restrict__ out)
{
    __shared__ float2 s_y[8][32];

    const int warp = threadIdx.x >> 5;
    const int lane = threadIdx.x & 31;
    const int gw = blockIdx.x * 8 + warp;
    const int b = gw >> 1;
    const int t = gw & 1;

    float2 se, pv;
    int sid = 0, pid = 0;

    if (b < B_SAMPLES) {
        const int* idx;
        const float2* tab;
        int s, e;
        if (t == 0) {
            s = g_p_off[b]; e = g_p_off[b + 1];
            idx = p_idx;
            tab = reinterpret_cast<const float2*>(imp_fact);
            // Finisher warp also prefetches the per-sample rows (independent).
            sid = __ldg(sci_ids + b);
            pid = __ldg(pap_ids + b);
            se = __ldg(reinterpret_cast<const float2*>(s_fact) + (size_t)sid * 32 + lane);
            pv = __ldg(reinterpret_cast<const float2*>(p_fact) + (size_t)pid * 32 + lane);
        } else {
            s = g_w_off[b]; e = g_w_off[b + 1];
            idx = w_idx;
            tab = reinterpret_cast<const float2*>(imp_wish);
        }

        float ax = 0.f, ay = 0.f;
        gather_shfl(idx, s, e, tab, lane, ax, ay);
        const float scale = rsqrtf(fmaxf((float)(e - s), 1.0f));
        s_y[warp][lane] = make_float2(ax * scale, ay * scale);
    }

    __syncthreads();

    if (t == 0 && b < B_SAMPLES) {
        float2 yp = s_y[warp][lane];
        float2 yw = s_y[warp + 1][lane];

        const float yx = yp.x + yw.x;
        const float yy = yp.y + yw.y;

        float d = (se.x + yx) * pv.x + (se.y + yy) * pv.y;

        #pragma unroll
        for (int off = 16; off > 0; off >>= 1)
            d += __shfl_xor_sync(0xFFFFFFFFu, d, off);

        if (lane == 0) {
            out[b] = d + __ldg(s_bias + sid) + __ldg(p_bias + pid) + __ldg(g_bias);
        }
    }
}

extern "C" void kernel_launch(void* const* d_in, const int* in_sizes, int n_in,
                              void* d_out, int out_size)
{
    const int*   sci_ids = (const int*)d_in[0];
    const int*   pap_ids = (const int*)d_in[1];
    const int*   p_idx   = (const int*)d_in[2];
    const int*   p_seg   = (const int*)d_in[3];
    const int*   w_idx   = (const int*)d_in[4];
    const int*   w_seg   = (const int*)d_in[5];
    const float* s_fact  = (const float*)d_in[6];
    const float* p_fact  = (const float*)d_in[7];
    const float* s_bias  = (const float*)d_in[8];
    const float* p_bias  = (const float*)d_in[9];
    const float* imp_f   = (const float*)d_in[10];
    const float* imp_w   = (const float*)d_in[11];
    const float* g_bias  = (const float*)d_in[12];
    float* out = (float*)d_out;

    const int TP = in_sizes[2];
    const int TW = in_sizes[4];

    // Pass 1: boundary-scan segment offsets (one thread per idx element).
    const int total = TP + TW;
    offsets_kernel<<<(total + 255) / 256, 256>>>(p_seg, TP, w_seg, TW);

    // Pass 2: two warps per sample (32768 warps), 8 warps per block.
    const int blocks = (B_SAMPLES * 2) / 8;
    svdpp_kernel<<<blocks, 256>>>(
        sci_ids, pap_ids, p_idx, w_idx,
        s_fact, p_fact, s_bias, p_bias, imp_f, imp_w, g_bias, out);
}

// round 7
// speedup vs baseline: 1.1483x; 1.1483x over previous
#include <cuda_runtime.h>
#include <math.h>

#define B_SAMPLES 16384
#define EMB 64

__device__ int g_p_off[B_SAMPLES + 1];
__device__ int g_w_off[B_SAMPLES + 1];

// Boundary-scan offsets: for sorted seg, off[v] = lower_bound(seg, v).
__device__ __forceinline__ void scan_one(const int* __restrict__ seg, int T,
                                         int* __restrict__ off, int i)
{
    int cur = __ldg(seg + i);
    int prev = (i == 0) ? -1 : __ldg(seg + i - 1);
    for (int v = prev + 1; v <= cur; v++) off[v] = i;
    if (i == T - 1) {
        for (int v = cur + 1; v <= B_SAMPLES; v++) off[v] = T;
    }
}

__global__ void __launch_bounds__(256) offsets_kernel(
    const int* __restrict__ p_seg, int TP,
    const int* __restrict__ w_seg, int TW)
{
    int t = blockIdx.x * blockDim.x + threadIdx.x;
    if (t < TP) {
        scan_one(p_seg, TP, g_p_off, t);
    } else if (t < TP + TW) {
        scan_one(w_seg, TW, g_w_off, t - TP);
    }
}

// Coalesced, clamped load of one 32-index chunk starting at i (requires i < e).
__device__ __forceinline__ int load_chunk(const int* __restrict__ idx,
                                          int i, int e, int lane)
{
    int rem = e - i;
    int pos = i + (lane < rem ? lane : rem - 1);
    return __ldg(idx + pos);
}

// Warp gather with shfl-broadcast indices and software-pipelined idx prefetch.
// c0 must hold the chunk at position s (if e > s). MLP=8 row loads per group.
__device__ __forceinline__ void gather_pipelined(
    const int* __restrict__ idx, int s, int e,
    const float2* __restrict__ t2, int lane, int c0,
    float& ax, float& ay)
{
    float sx[8], sy[8];
    #pragma unroll
    for (int k = 0; k < 8; k++) { sx[k] = 0.f; sy[k] = 0.f; }

    int i = s;
    int c = c0;
    while (i < e) {
        const int next_i = i + 32;
        int c_next = 0;
        if (next_i < e) c_next = load_chunk(idx, next_i, e, lane);  // prefetch

        const int cnt = (e - i < 32) ? (e - i) : 32;
        if (cnt == 32) {
            #pragma unroll
            for (int k0 = 0; k0 < 32; k0 += 8) {
                int r[8];
                #pragma unroll
                for (int k = 0; k < 8; k++)
                    r[k] = __shfl_sync(0xFFFFFFFFu, c, k0 + k);
                float2 v[8];
                #pragma unroll
                for (int k = 0; k < 8; k++)
                    v[k] = __ldg(t2 + (size_t)r[k] * 32 + lane);
                #pragma unroll
                for (int k = 0; k < 8; k++) { sx[k] += v[k].x; sy[k] += v[k].y; }
            }
        } else {
            int k = 0;
            for (; k + 8 <= cnt; k += 8) {
                int r[8];
                #pragma unroll
                for (int j = 0; j < 8; j++)
                    r[j] = __shfl_sync(0xFFFFFFFFu, c, k + j);
                float2 v[8];
                #pragma unroll
                for (int j = 0; j < 8; j++)
                    v[j] = __ldg(t2 + (size_t)r[j] * 32 + lane);
                #pragma unroll
                for (int j = 0; j < 8; j++) { sx[j] += v[j].x; sy[j] += v[j].y; }
            }
            for (; k < cnt; k++) {
                int r = __shfl_sync(0xFFFFFFFFu, c, k);
                float2 v = __ldg(t2 + (size_t)r * 32 + lane);
                sx[0] += v.x; sy[0] += v.y;
            }
        }
        i = next_i;
        c = c_next;
    }

    ax = ((sx[0] + sx[1]) + (sx[2] + sx[3])) + ((sx[4] + sx[5]) + (sx[6] + sx[7]));
    ay = ((sy[0] + sy[1]) + (sy[2] + sy[3])) + ((sy[4] + sy[5]) + (sy[6] + sy[7]));
}

__global__ void __launch_bounds__(256) svdpp_kernel(
    const int* __restrict__ sci_ids,
    const int* __restrict__ pap_ids,
    const int* __restrict__ p_idx,
    const int* __restrict__ w_idx,
    const float* __restrict__ s_fact,
    const float* __restrict__ p_fact,
    const float* __restrict__ s_bias,
    const float* __restrict__ p_bias,
    const float* __restrict__ imp_fact,
    const float* __restrict__ imp_wish,
    const float* __restrict__ g_bias,
    float* __restrict__ out)
{
    const int warp_id = (blockIdx.x * blockDim.x + threadIdx.x) >> 5;
    if (warp_id >= B_SAMPLES) return;
    const int b = warp_id;
    const int lane = threadIdx.x & 31;

    const int ps = g_p_off[b];
    const int pe = g_p_off[b + 1];
    const int ws = g_w_off[b];
    const int we = g_w_off[b + 1];

    // Front-batch independent loads: both first idx chunks + per-sample rows.
    int c_p = 0, c_w = 0;
    if (pe > ps) c_p = load_chunk(p_idx, ps, pe, lane);
    if (we > ws) c_w = load_chunk(w_idx, ws, we, lane);

    const int sid = __ldg(sci_ids + b);
    const int pid = __ldg(pap_ids + b);
    float2 se = __ldg(reinterpret_cast<const float2*>(s_fact) + (size_t)sid * 32 + lane);
    float2 pv = __ldg(reinterpret_cast<const float2*>(p_fact) + (size_t)pid * 32 + lane);

    float px = 0.f, py = 0.f;
    gather_pipelined(p_idx, ps, pe,
                     reinterpret_cast<const float2*>(imp_fact), lane, c_p, px, py);
    const float pscale = rsqrtf(fmaxf((float)(pe - ps), 1.0f));

    float wx = 0.f, wy = 0.f;
    gather_pipelined(w_idx, ws, we,
                     reinterpret_cast<const float2*>(imp_wish), lane, c_w, wx, wy);
    const float wscale = rsqrtf(fmaxf((float)(we - ws), 1.0f));

    const float yx = px * pscale + wx * wscale;
    const float yy = py * pscale + wy * wscale;

    float d = (se.x + yx) * pv.x + (se.y + yy) * pv.y;

    #pragma unroll
    for (int off = 16; off > 0; off >>= 1)
        d += __shfl_xor_sync(0xFFFFFFFFu, d, off);

    if (lane == 0) {
        out[b] = d + __ldg(s_bias + sid) + __ldg(p_bias + pid) + __ldg(g_bias);
    }
}

extern "C" void kernel_launch(void* const* d_in, const int* in_sizes, int n_in,
                              void* d_out, int out_size)
{
    const int*   sci_ids = (const int*)d_in[0];
    const int*   pap_ids = (const int*)d_in[1];
    const int*   p_idx   = (const int*)d_in[2];
    const int*   p_seg   = (const int*)d_in[3];
    const int*   w_idx   = (const int*)d_in[4];
    const int*   w_seg   = (const int*)d_in[5];
    const float* s_fact  = (const float*)d_in[6];
    const float* p_fact  = (const float*)d_in[7];
    const float* s_bias  = (const float*)d_in[8];
    const float* p_bias  = (const float*)d_in[9];
    const float* imp_f   = (const float*)d_in[10];
    const float* imp_w   = (const float*)d_in[11];
    const float* g_bias  = (const float*)d_in[12];
    float* out = (float*)d_out;

    const int TP = in_sizes[2];
    const int TW = in_sizes[4];

    // Pass 1: boundary-scan segment offsets (one thread per idx element).
    const int total = TP + TW;
    offsets_kernel<<<(total + 255) / 256, 256>>>(p_seg, TP, w_seg, TW);

    // Pass 2: one warp per sample.
    const int threads = 256;
    const int blocks = B_SAMPLES / (threads / 32);
    svdpp_kernel<<<blocks, threads>>>(
        sci_ids, pap_ids, p_idx, w_idx,
        s_fact, p_fact, s_bias, p_bias, imp_f, imp_w, g_bias, out);
}